// round 9
// baseline (speedup 1.0000x reference)
#include <cuda_runtime.h>
#include <cuda_bf16.h>
#include <cstdint>

#define BB 32
#define TT 2048
#define II 256
#define HH 512
#define GG 2048   // 4*H

#define NREC 64
#define NPROD 84
#define NCTA (NREC + NPROD)
#define NTH  256

// Scratch (device globals — zero-initialized; no runtime allocation)
__device__ float g_xg[134217728];            // [t][g][b] fp32 (512 MB)
__device__ uint32_t g_xp[BB * TT * II];      // x packed hi|lo bf16 (64 MB)
__device__ uint32_t g_wp[GG * II];           // W_ih packed hi|lo (2 MB)
__device__ uint32_t g_hp[2][BB * HH];        // ping-pong hidden, packed hi|lo
__device__ int g_flag[NREC * 32];            // per-rec-CTA monotonic flags (128B apart)
__device__ int g_xgf[TT];                    // per-t producer flags (== epoch when ready)
__device__ int g_epoch;                      // bumped once per replay by conv kernel

// ---------------------------------------------------------------------------
// helpers
// ---------------------------------------------------------------------------
__device__ __forceinline__ uint32_t packhl(float v) {
    __nv_bfloat16 h = __float2bfloat16(v);
    float r = v - __bfloat162float(h);
    __nv_bfloat16 lo = __float2bfloat16(r);
    unsigned short uh = *reinterpret_cast<unsigned short*>(&h);
    unsigned short ul = *reinterpret_cast<unsigned short*>(&lo);
    return (uint32_t)uh | ((uint32_t)ul << 16);
}

__device__ __forceinline__ void split2(float x, float y, uint32_t& hi, uint32_t& lo) {
    __nv_bfloat162 h = __floats2bfloat162_rn(x, y);
    float rx = x - __bfloat162float(h.x);
    float ry = y - __bfloat162float(h.y);
    __nv_bfloat162 l = __floats2bfloat162_rn(rx, ry);
    hi = *(uint32_t*)&h;
    lo = *(uint32_t*)&l;
}

__device__ __forceinline__ void mma_bf16(float* c,
                                         uint32_t a0, uint32_t a1, uint32_t a2, uint32_t a3,
                                         uint32_t b0, uint32_t b1) {
    asm volatile(
        "mma.sync.aligned.m16n8k16.row.col.f32.bf16.bf16.f32 "
        "{%0,%1,%2,%3}, {%4,%5,%6,%7}, {%8,%9}, {%0,%1,%2,%3};"
        : "+f"(c[0]), "+f"(c[1]), "+f"(c[2]), "+f"(c[3])
        : "r"(a0), "r"(a1), "r"(a2), "r"(a3), "r"(b0), "r"(b1));
}

__device__ __forceinline__ float sigf(float v) {
    return __fdividef(1.0f, 1.0f + __expf(-v));
}
__device__ __forceinline__ float tanhfast(float v) {
    return __fdividef(2.0f, 1.0f + __expf(-2.0f * v)) - 1.0f;
}

__device__ __forceinline__ uint32_t smem_u32(const void* p) {
    uint32_t a;
    asm("{ .reg .u64 t; cvta.to.shared.u64 t, %1; cvt.u32.u64 %0, t; }" : "=r"(a) : "l"(p));
    return a;
}
__device__ __forceinline__ void cp_async16(uint32_t dst, const void* src) {
    asm volatile("cp.async.ca.shared.global [%0], [%1], 16;" :: "r"(dst), "l"(src) : "memory");
}

// Load 4 B-fragments (bh0,bh1,bl0,bl1) from a packed hi|lo u32 row.
__device__ __forceinline__ void load_bfrag(uint32_t f[4], const uint32_t* __restrict__ rp) {
    uint2 ca = __ldcg((const uint2*)rp);
    uint2 cb = __ldcg((const uint2*)(rp + 8));
    f[0] = __byte_perm(ca.x, ca.y, 0x5410);
    f[2] = __byte_perm(ca.x, ca.y, 0x7632);
    f[1] = __byte_perm(cb.x, cb.y, 0x5410);
    f[3] = __byte_perm(cb.x, cb.y, 0x7632);
}

// ---------------------------------------------------------------------------
// Kernel 0: pack x and W_ih to hi|lo planes; bump epoch.
// ---------------------------------------------------------------------------
__global__ void __launch_bounds__(256) conv_kernel(const float* __restrict__ x,
                                                   const float* __restrict__ Wih) {
    if (blockIdx.x == 0 && threadIdx.x == 0) g_epoch = g_epoch + 1;
    const size_t Nx = (size_t)BB * TT * II;
    const size_t Nw = (size_t)GG * II;
    for (size_t i = blockIdx.x * 256 + threadIdx.x; i < Nx + Nw; i += (size_t)gridDim.x * 256) {
        if (i < Nx) g_xp[i] = packhl(x[i]);
        else        g_wp[i - Nx] = packhl(Wih[i - Nx]);
    }
}

// smem layout (bytes) — rec role only
#define SM_RED 0                     // 8*32*36*4 = 36864  (f32 [8][32][36])
#define SM_XG  36864                 // 2 bufs x [32 g][36 f] f32 = 9216
#define SM_TOT 46080

// ---------------------------------------------------------------------------
// Fused kernel: blockIdx < 64 -> recurrence role; else -> xg producer role.
// ---------------------------------------------------------------------------
__global__ void __launch_bounds__(NTH, 1) lstm_all(
    const float* __restrict__ h0,
    const float* __restrict__ c0,
    const float* __restrict__ Whh,
    const float* __restrict__ bih,
    const float* __restrict__ bhh,
    float* __restrict__ out,
    long long out_size)
{
    extern __shared__ char smem[];
    const int tid = threadIdx.x;
    const int cta = blockIdx.x;
    const int w  = tid >> 5;
    const int l  = tid & 31;
    const int g4 = l >> 2;
    const int t4 = l & 3;
    const int epoch = *(volatile int*)&g_epoch;

    // =======================================================================
    // PRODUCER role: xg[t][g][b] = W_ih * x[t]  (3-pass bf16, fp32 out)
    // =======================================================================
    if (cta >= NREC) {
        const int pc = cta - NREC;
        for (int t = pc; t < TT; t += NPROD) {
#pragma unroll 1
            for (int mc = 0; mc < 4; mc++) {
                float acc[4][4][4] = {};
#pragma unroll 1
                for (int kt = 0; kt < 16; kt++) {
                    const int k = 16 * kt + 2 * t4;
                    uint32_t bx[4][4];
#pragma unroll
                    for (int nt = 0; nt < 4; nt++)
                        load_bfrag(bx[nt], g_xp + ((size_t)(8 * nt + g4) * TT + t) * II + k);
#pragma unroll
                    for (int mt = 0; mt < 4; mt++) {
                        const int r0 = 256 * w + 64 * mc + 16 * mt + g4;
                        const uint32_t* q0 = g_wp + (size_t)r0 * II + k;
                        uint2 a0 = __ldcg((const uint2*)q0);
                        uint2 a1 = __ldcg((const uint2*)(q0 + 8 * II));
                        uint2 a2 = __ldcg((const uint2*)(q0 + 8));
                        uint2 a3 = __ldcg((const uint2*)(q0 + 8 * II + 8));
                        uint32_t ahi[4], alo[4];
                        ahi[0] = __byte_perm(a0.x, a0.y, 0x5410); alo[0] = __byte_perm(a0.x, a0.y, 0x7632);
                        ahi[1] = __byte_perm(a1.x, a1.y, 0x5410); alo[1] = __byte_perm(a1.x, a1.y, 0x7632);
                        ahi[2] = __byte_perm(a2.x, a2.y, 0x5410); alo[2] = __byte_perm(a2.x, a2.y, 0x7632);
                        ahi[3] = __byte_perm(a3.x, a3.y, 0x5410); alo[3] = __byte_perm(a3.x, a3.y, 0x7632);
#pragma unroll
                        for (int nt = 0; nt < 4; nt++) {
                            mma_bf16(acc[mt][nt], ahi[0], ahi[1], ahi[2], ahi[3], bx[nt][0], bx[nt][1]);
                            mma_bf16(acc[mt][nt], ahi[0], ahi[1], ahi[2], ahi[3], bx[nt][2], bx[nt][3]);
                            mma_bf16(acc[mt][nt], alo[0], alo[1], alo[2], alo[3], bx[nt][0], bx[nt][1]);
                        }
                    }
                }
#pragma unroll
                for (int mt = 0; mt < 4; mt++) {
                    const int gr = 256 * w + 64 * mc + 16 * mt + g4;
#pragma unroll
                    for (int nt = 0; nt < 4; nt++) {
                        const int b = 8 * nt + 2 * t4;
                        float* o = g_xg + ((size_t)t * GG + gr) * BB + b;
                        *(float2*)o = make_float2(acc[mt][nt][0], acc[mt][nt][1]);
                        *(float2*)(o + 8 * BB) = make_float2(acc[mt][nt][2], acc[mt][nt][3]);
                    }
                }
            }
            __threadfence();
            __syncthreads();
            if (tid == 0) *(volatile int*)&g_xgf[t] = epoch;
        }
        return;
    }

    // =======================================================================
    // RECURRENCE role (64 CTAs): 8 H-cols each; W_hh GEMM K-split 8 warps.
    // =======================================================================
    float* redp = (float*)(smem + SM_RED);
    float* xgp  = (float*)(smem + SM_XG);
    const int col0 = cta * 8;

    // --- W_hh fragments (hi/lo) in registers ---
    uint32_t whi[2][4][4], wlo[2][4][4];
#pragma unroll
    for (int mt = 0; mt < 2; mt++)
#pragma unroll
        for (int kt = 0; kt < 4; kt++) {
            const int k = 64 * w + 16 * kt + 2 * t4;
            const int r0 = mt * 16 + g4;
            const int r1 = r0 + 8;
            const int grow0 = (r0 >> 3) * HH + col0 + (r0 & 7);
            const int grow1 = (r1 >> 3) * HH + col0 + (r1 & 7);
            float2 v;
            v = *(const float2*)(Whh + (size_t)grow0 * HH + k);
            split2(v.x, v.y, whi[mt][kt][0], wlo[mt][kt][0]);
            v = *(const float2*)(Whh + (size_t)grow1 * HH + k);
            split2(v.x, v.y, whi[mt][kt][1], wlo[mt][kt][1]);
            v = *(const float2*)(Whh + (size_t)grow0 * HH + k + 8);
            split2(v.x, v.y, whi[mt][kt][2], wlo[mt][kt][2]);
            v = *(const float2*)(Whh + (size_t)grow1 * HH + k + 8);
            split2(v.x, v.y, whi[mt][kt][3], wlo[mt][kt][3]);
        }

    // --- activation identity + per-thread state ---
    const int colL = tid & 7;
    const int b_act = tid >> 3;
    const int colG = col0 + colL;
    float c_reg = c0[b_act * HH + colG];
    float bias_r[4];
#pragma unroll
    for (int g = 0; g < 4; g++)
        bias_r[g] = bih[g * HH + colG] + bhh[g * HH + colG];

    // --- flag base (own flag; monotonic across replays) ---
    const int F = *(volatile int*)&g_flag[cta * 32];

    // --- publish h0 slice (packed) ---
    g_hp[0][b_act * HH + colG] = packhl(h0[b_act * HH + colG]);
    __threadfence();
    __syncthreads();
    if (tid == 0) *(volatile int*)&g_flag[cta * 32] = F + 1;

    // --- initial xg[0] load into buf0 ---
    const int xg_gl = tid >> 3;             // 0..31  (gate*8 + colL)
    const int xg_c8 = tid & 7;              // 16B chunk
    const int xg_gg = (xg_gl >> 3) * HH + col0 + (xg_gl & 7);
    {
        while (*(volatile int*)&g_xgf[0] < epoch) __nanosleep(100);
        const float* src = g_xg + ((size_t)0 * GG + xg_gg) * BB + 4 * xg_c8;
        cp_async16(smem_u32(smem + SM_XG) + xg_gl * 144 + xg_c8 * 16, src);
        asm volatile("cp.async.commit_group;" ::: "memory");
    }

    const long long BTH = (long long)BB * TT * HH;
    const bool tails = (out_size >= BTH + 2LL * BB * HH);

    const int pidx = (8 * w + (l & 7)) * 32;   // producer flag index
    const bool poller = (l < 8);
    const int kbase = 64 * w + 2 * t4;

    for (int t = 0; t < TT; t++) {
        // ---- prefetch xg[t+1] (a full step of latency to land) ----
        if (t + 1 < TT) {
            while (*(volatile int*)&g_xgf[t + 1] < epoch) __nanosleep(40);
            const float* src = g_xg + ((size_t)(t + 1) * GG + xg_gg) * BB + 4 * xg_c8;
            cp_async16(smem_u32(smem + SM_XG) + ((t + 1) & 1) * 4608 + xg_gl * 144 + xg_c8 * 16, src);
        }
        asm volatile("cp.async.commit_group;" ::: "memory");

        // ---- poll h flags (lanes<8 only) ----
        {
            const int need = F + t + 1;
            while (__any_sync(0xffffffffu,
                              poller && (*(volatile int*)&g_flag[pidx] < need)))
                __nanosleep(20);
        }
        __threadfence();   // acquire

        // ---- load ALL h B-frags (16 LDG.64 in flight), then 96 MMAs ----
        const uint32_t* hp = g_hp[t & 1];
        uint32_t f[4][4][4];
#pragma unroll
        for (int g = 0; g < 4; g++)
#pragma unroll
            for (int nt = 0; nt < 4; nt++)
                load_bfrag(f[g][nt], hp + (size_t)(8 * nt + g4) * HH + kbase + 16 * g);

        float acc[2][4][4] = {};
#pragma unroll
        for (int g = 0; g < 4; g++)
#pragma unroll
            for (int nt = 0; nt < 4; nt++)
#pragma unroll
                for (int mt = 0; mt < 2; mt++) {
                    mma_bf16(acc[mt][nt], whi[mt][g][0], whi[mt][g][1], whi[mt][g][2], whi[mt][g][3], f[g][nt][0], f[g][nt][1]);
                    mma_bf16(acc[mt][nt], whi[mt][g][0], whi[mt][g][1], whi[mt][g][2], whi[mt][g][3], f[g][nt][2], f[g][nt][3]);
                    mma_bf16(acc[mt][nt], wlo[mt][g][0], wlo[mt][g][1], wlo[mt][g][2], wlo[mt][g][3], f[g][nt][0], f[g][nt][1]);
                }

        // ---- store split-K partials: red[w][row][b], pitch 36 ----
        {
            float* rw = redp + w * 1152;
#pragma unroll
            for (int mt = 0; mt < 2; mt++)
#pragma unroll
                for (int nt = 0; nt < 4; nt++) {
                    int row0 = mt * 16 + g4;
                    int cc = 8 * nt + 2 * t4;
                    *(float2*)&rw[row0 * 36 + cc] = make_float2(acc[mt][nt][0], acc[mt][nt][1]);
                    *(float2*)&rw[(row0 + 8) * 36 + cc] = make_float2(acc[mt][nt][2], acc[mt][nt][3]);
                }
        }
        asm volatile("cp.async.wait_group 1;" ::: "memory");
        __syncthreads();

        // ---- reduce + xg + bias + activations + publish ----
        {
            const float* xb = xgp + (t & 1) * 1152;
            float gv[4];
#pragma unroll
            for (int g = 0; g < 4; g++) {
                float s = bias_r[g] + xb[(g * 8 + colL) * 36 + b_act];
                const int row = g * 8 + colL;
#pragma unroll
                for (int w2 = 0; w2 < 8; w2++)
                    s += redp[w2 * 1152 + row * 36 + b_act];
                gv[g] = s;
            }
            float ig = sigf(gv[0]);
            float fg = sigf(gv[1]);
            float gt = tanhfast(gv[2]);
            float og = sigf(gv[3]);
            float cn = fmaf(fg, c_reg, ig * gt);
            float hn = og * tanhfast(cn);
            c_reg = cn;

            g_hp[(t + 1) & 1][b_act * HH + colG] = packhl(hn);
            __threadfence();
            __syncthreads();
            if (tid == 0) *(volatile int*)&g_flag[cta * 32] = F + t + 2;

            // output stores off the critical path
            out[((size_t)b_act * TT + t) * HH + colG] = hn;
            if (t == TT - 1 && tails) {
                out[BTH + (long long)b_act * HH + colG] = hn;
                out[BTH + (long long)BB * HH + (long long)b_act * HH + colG] = cn;
            }
        }
    }
}

// ---------------------------------------------------------------------------
// Inputs (metadata order): x, h0, c0, W_ih, W_hh, b_ih, b_hh
// Output: concat(result[B,T,H], h_f[1,B,H], c_f[1,B,H])
// ---------------------------------------------------------------------------
extern "C" void kernel_launch(void* const* d_in, const int* in_sizes, int n_in,
                              void* d_out, int out_size) {
    const float* x   = (const float*)d_in[0];
    const float* h0  = (const float*)d_in[1];
    const float* c0  = (const float*)d_in[2];
    const float* Wih = (const float*)d_in[3];
    const float* Whh = (const float*)d_in[4];
    const float* bih = (const float*)d_in[5];
    const float* bhh = (const float*)d_in[6];
    float* out = (float*)d_out;

    cudaFuncSetAttribute(lstm_all, cudaFuncAttributeMaxDynamicSharedMemorySize, SM_TOT);

    conv_kernel<<<2048, 256>>>(x, Wih);
    lstm_all<<<NCTA, NTH, SM_TOT>>>(h0, c0, Whh, bih, bhh, out, (long long)out_size);
}

// round 10
// speedup vs baseline: 1.2663x; 1.2663x over previous
#include <cuda_runtime.h>
#include <cuda_bf16.h>
#include <cstdint>

#define BB 32
#define TT 2048
#define II 256
#define HH 512
#define GG 2048   // 4*H

#define NREC 128
#define NTH  256

// Scratch (device globals — zero-initialized; no runtime allocation)
__device__ float g_xg[134217728];            // [t][g][b] fp32 (512 MB)
__device__ uint32_t g_xp[BB * TT * II];      // x packed hi|lo bf16 (64 MB)
__device__ uint32_t g_wp[GG * II];           // W_ih packed hi|lo (2 MB)
__device__ uint32_t g_hp[2][BB * HH];        // ping-pong hidden, packed hi|lo
__device__ int g_flag[NREC * 32];            // per-rec-CTA monotonic flags (128B apart)

// ---------------------------------------------------------------------------
// helpers
// ---------------------------------------------------------------------------
__device__ __forceinline__ uint32_t packhl(float v) {
    __nv_bfloat16 h = __float2bfloat16(v);
    float r = v - __bfloat162float(h);
    __nv_bfloat16 lo = __float2bfloat16(r);
    unsigned short uh = *reinterpret_cast<unsigned short*>(&h);
    unsigned short ul = *reinterpret_cast<unsigned short*>(&lo);
    return (uint32_t)uh | ((uint32_t)ul << 16);
}

__device__ __forceinline__ void split2(float x, float y, uint32_t& hi, uint32_t& lo) {
    __nv_bfloat162 h = __floats2bfloat162_rn(x, y);
    float rx = x - __bfloat162float(h.x);
    float ry = y - __bfloat162float(h.y);
    __nv_bfloat162 l = __floats2bfloat162_rn(rx, ry);
    hi = *(uint32_t*)&h;
    lo = *(uint32_t*)&l;
}

__device__ __forceinline__ void mma_bf16(float* c,
                                         uint32_t a0, uint32_t a1, uint32_t a2, uint32_t a3,
                                         uint32_t b0, uint32_t b1) {
    asm volatile(
        "mma.sync.aligned.m16n8k16.row.col.f32.bf16.bf16.f32 "
        "{%0,%1,%2,%3}, {%4,%5,%6,%7}, {%8,%9}, {%0,%1,%2,%3};"
        : "+f"(c[0]), "+f"(c[1]), "+f"(c[2]), "+f"(c[3])
        : "r"(a0), "r"(a1), "r"(a2), "r"(a3), "r"(b0), "r"(b1));
}

__device__ __forceinline__ float sigf(float v) {
    return __fdividef(1.0f, 1.0f + __expf(-v));
}
__device__ __forceinline__ float tanhfast(float v) {
    return __fdividef(2.0f, 1.0f + __expf(-2.0f * v)) - 1.0f;
}

__device__ __forceinline__ uint32_t smem_u32(const void* p) {
    uint32_t a;
    asm("{ .reg .u64 t; cvta.to.shared.u64 t, %1; cvt.u32.u64 %0, t; }" : "=r"(a) : "l"(p));
    return a;
}
__device__ __forceinline__ void cp_async16(uint32_t dst, const void* src) {
    asm volatile("cp.async.ca.shared.global [%0], [%1], 16;" :: "r"(dst), "l"(src) : "memory");
}

// Load 4 B-fragments (bh0,bh1,bl0,bl1) from a packed hi|lo u32 row.
__device__ __forceinline__ void load_bfrag(uint32_t f[4], const uint32_t* __restrict__ rp) {
    uint2 ca = __ldcg((const uint2*)rp);
    uint2 cb = __ldcg((const uint2*)(rp + 8));
    f[0] = __byte_perm(ca.x, ca.y, 0x5410);
    f[2] = __byte_perm(ca.x, ca.y, 0x7632);
    f[1] = __byte_perm(cb.x, cb.y, 0x5410);
    f[3] = __byte_perm(cb.x, cb.y, 0x7632);
}

// ---------------------------------------------------------------------------
// Kernel 0: pack x and W_ih to hi|lo planes.
// ---------------------------------------------------------------------------
__global__ void __launch_bounds__(256) conv_kernel(const float* __restrict__ x,
                                                   const float* __restrict__ Wih) {
    const size_t Nx = (size_t)BB * TT * II;
    const size_t Nw = (size_t)GG * II;
    for (size_t i = blockIdx.x * 256 + threadIdx.x; i < Nx + Nw; i += (size_t)gridDim.x * 256) {
        if (i < Nx) g_xp[i] = packhl(x[i]);
        else        g_wp[i - Nx] = packhl(Wih[i - Nx]);
    }
}

// ---------------------------------------------------------------------------
// Kernel 1: xg[t][g][b] = W_ih * x[t]  (3-pass bf16 tensor GEMM, fp32 out)
// 148 CTAs x 256 thr; CTA handles t = bid, bid+148, ...
// ---------------------------------------------------------------------------
__global__ void __launch_bounds__(NTH) xg_kernel() {
    const int tid = threadIdx.x;
    const int w  = tid >> 5;
    const int l  = tid & 31;
    const int g4 = l >> 2;
    const int t4 = l & 3;

    for (int t = blockIdx.x; t < TT; t += gridDim.x) {
#pragma unroll 1
        for (int mc = 0; mc < 4; mc++) {
            float acc[4][4][4] = {};
#pragma unroll 1
            for (int kt = 0; kt < 16; kt++) {
                const int k = 16 * kt + 2 * t4;
                uint32_t bx[4][4];
#pragma unroll
                for (int nt = 0; nt < 4; nt++)
                    load_bfrag(bx[nt], g_xp + ((size_t)(8 * nt + g4) * TT + t) * II + k);
#pragma unroll
                for (int mt = 0; mt < 4; mt++) {
                    const int r0 = 256 * w + 64 * mc + 16 * mt + g4;
                    const uint32_t* q0 = g_wp + (size_t)r0 * II + k;
                    uint2 a0 = __ldcg((const uint2*)q0);
                    uint2 a1 = __ldcg((const uint2*)(q0 + 8 * II));
                    uint2 a2 = __ldcg((const uint2*)(q0 + 8));
                    uint2 a3 = __ldcg((const uint2*)(q0 + 8 * II + 8));
                    uint32_t ahi[4], alo[4];
                    ahi[0] = __byte_perm(a0.x, a0.y, 0x5410); alo[0] = __byte_perm(a0.x, a0.y, 0x7632);
                    ahi[1] = __byte_perm(a1.x, a1.y, 0x5410); alo[1] = __byte_perm(a1.x, a1.y, 0x7632);
                    ahi[2] = __byte_perm(a2.x, a2.y, 0x5410); alo[2] = __byte_perm(a2.x, a2.y, 0x7632);
                    ahi[3] = __byte_perm(a3.x, a3.y, 0x5410); alo[3] = __byte_perm(a3.x, a3.y, 0x7632);
#pragma unroll
                    for (int nt = 0; nt < 4; nt++) {
                        mma_bf16(acc[mt][nt], ahi[0], ahi[1], ahi[2], ahi[3], bx[nt][0], bx[nt][1]);
                        mma_bf16(acc[mt][nt], ahi[0], ahi[1], ahi[2], ahi[3], bx[nt][2], bx[nt][3]);
                        mma_bf16(acc[mt][nt], alo[0], alo[1], alo[2], alo[3], bx[nt][0], bx[nt][1]);
                    }
                }
            }
#pragma unroll
            for (int mt = 0; mt < 4; mt++) {
                const int gr = 256 * w + 64 * mc + 16 * mt + g4;
#pragma unroll
                for (int nt = 0; nt < 4; nt++) {
                    const int b = 8 * nt + 2 * t4;
                    float* o = g_xg + ((size_t)t * GG + gr) * BB + b;
                    *(float2*)o = make_float2(acc[mt][nt][0], acc[mt][nt][1]);
                    *(float2*)(o + 8 * BB) = make_float2(acc[mt][nt][2], acc[mt][nt][3]);
                }
            }
        }
    }
}

// smem layout (bytes) — rec kernel
#define SM_RED 0                     // 8 * 16*40 * 4 = 20480   (f32 [8][16][40])
#define SM_XG  20480                 // 2 bufs x [16][40] f32 = 5120
#define SM_TOT 25600

// ---------------------------------------------------------------------------
// Kernel 2: persistent recurrence. 128 CTAs x 256 threads.
// CTA owns 4 H-cols -> 16 gate rows (r = gate*4 + colL).
// gates = W_hh*h (K=512, 8-way warp K-split, 48 MMAs/warp 3-pass) + xg + bias.
// xg guaranteed ready (kernel ordering); h via per-CTA monotonic flags.
// ---------------------------------------------------------------------------
__global__ void __launch_bounds__(NTH, 1) lstm_rec(
    const float* __restrict__ h0,
    const float* __restrict__ c0,
    const float* __restrict__ Whh,
    const float* __restrict__ bih,
    const float* __restrict__ bhh,
    float* __restrict__ out,
    long long out_size)
{
    extern __shared__ char smem[];
    float* redp = (float*)(smem + SM_RED);
    float* xgp  = (float*)(smem + SM_XG);

    const int tid = threadIdx.x;
    const int cta = blockIdx.x;
    const int col0 = cta * 4;

    const int w  = tid >> 5;
    const int l  = tid & 31;
    const int g4 = l >> 2;
    const int t4 = l & 3;

    // --- W_hh fragments (hi/lo) in registers: 16 rows x this warp's K=64 ---
    uint32_t whi[4][4], wlo[4][4];
#pragma unroll
    for (int kt = 0; kt < 4; kt++) {
        const int k = 64 * w + 16 * kt + 2 * t4;
        const int r0 = g4;
        const int r1 = g4 + 8;
        const int grow0 = (r0 >> 2) * HH + col0 + (r0 & 3);
        const int grow1 = (r1 >> 2) * HH + col0 + (r1 & 3);
        float2 v;
        v = *(const float2*)(Whh + (size_t)grow0 * HH + k);
        split2(v.x, v.y, whi[kt][0], wlo[kt][0]);
        v = *(const float2*)(Whh + (size_t)grow1 * HH + k);
        split2(v.x, v.y, whi[kt][1], wlo[kt][1]);
        v = *(const float2*)(Whh + (size_t)grow0 * HH + k + 8);
        split2(v.x, v.y, whi[kt][2], wlo[kt][2]);
        v = *(const float2*)(Whh + (size_t)grow1 * HH + k + 8);
        split2(v.x, v.y, whi[kt][3], wlo[kt][3]);
    }

    // --- activation identity (tid<128): colL = tid&3, b = tid>>2 ---
    const int colL = tid & 3;
    const int b_act = tid >> 2;
    const int colG = col0 + colL;
    float c_reg = 0.f, bias_r[4] = {};
    if (tid < 128) {
        c_reg = c0[b_act * HH + colG];
#pragma unroll
        for (int g = 0; g < 4; g++)
            bias_r[g] = bih[g * HH + colG] + bhh[g * HH + colG];
    }

    // --- flag base (own flag; monotonic across replays) ---
    const int F = *(volatile int*)&g_flag[cta * 32];

    // --- publish h0 slice (packed) ---
    if (tid < 128) g_hp[0][b_act * HH + colG] = packhl(h0[b_act * HH + colG]);
    __threadfence();
    __syncthreads();
    if (tid == 0) *(volatile int*)&g_flag[cta * 32] = F + 1;

    // --- initial xg[0] load into buf0 (xg guaranteed complete) ---
    const int xg_gl = tid >> 3;             // 0..15 for tid<128
    const int xg_c8 = tid & 7;
    const int xg_gg = (xg_gl >> 2) * HH + col0 + (xg_gl & 3);
    if (tid < 128) {
        const float* src = g_xg + ((size_t)0 * GG + xg_gg) * BB + 4 * xg_c8;
        cp_async16(smem_u32(smem + SM_XG) + xg_gl * 160 + xg_c8 * 16, src);
    }
    asm volatile("cp.async.commit_group;" ::: "memory");

    const long long BTH = (long long)BB * TT * HH;
    const bool tails = (out_size >= BTH + 2LL * BB * HH);

    const int pidx = (16 * w + (l & 15)) * 32;   // producer flag index
    const bool poller = (l < 16);
    const int kbase = 64 * w + 2 * t4;

    for (int t = 0; t < TT; t++) {
        // ---- prefetch xg[t+1] (whole step to land) ----
        if (t + 1 < TT && tid < 128) {
            const float* src = g_xg + ((size_t)(t + 1) * GG + xg_gg) * BB + 4 * xg_c8;
            cp_async16(smem_u32(smem + SM_XG) + ((t + 1) & 1) * 2560 + xg_gl * 160 + xg_c8 * 16, src);
        }
        asm volatile("cp.async.commit_group;" ::: "memory");

        // ---- poll h flags (lanes<16 only; short-circuit keeps others quiet) ----
        {
            const int need = F + t + 1;
            while (__any_sync(0xffffffffu,
                              poller && (*(volatile int*)&g_flag[pidx] < need)))
                __nanosleep(32);
        }
        __threadfence();   // acquire

        // ---- load ALL h B-frags (16 LDG.64 in flight), then 48 MMAs ----
        const uint32_t* hp = g_hp[t & 1];
        uint32_t f[4][4][4];
#pragma unroll
        for (int g = 0; g < 4; g++)
#pragma unroll
            for (int nt = 0; nt < 4; nt++)
                load_bfrag(f[g][nt], hp + (size_t)(8 * nt + g4) * HH + kbase + 16 * g);

        float acc[4][4] = {};
#pragma unroll
        for (int g = 0; g < 4; g++)
#pragma unroll
            for (int nt = 0; nt < 4; nt++) {
                mma_bf16(acc[nt], whi[g][0], whi[g][1], whi[g][2], whi[g][3], f[g][nt][0], f[g][nt][1]);
                mma_bf16(acc[nt], whi[g][0], whi[g][1], whi[g][2], whi[g][3], f[g][nt][2], f[g][nt][3]);
                mma_bf16(acc[nt], wlo[g][0], wlo[g][1], wlo[g][2], wlo[g][3], f[g][nt][0], f[g][nt][1]);
            }

        // ---- store split-K partials: red[w][row][b], pitch 40 ----
        {
            float* rw = redp + w * 640;
#pragma unroll
            for (int nt = 0; nt < 4; nt++) {
                int cc = 8 * nt + 2 * t4;
                *(float2*)&rw[g4 * 40 + cc] = make_float2(acc[nt][0], acc[nt][1]);
                *(float2*)&rw[(g4 + 8) * 40 + cc] = make_float2(acc[nt][2], acc[nt][3]);
            }
        }
        asm volatile("cp.async.wait_group 1;" ::: "memory");
        __syncthreads();

        // ---- reduce + xg + bias + activations + publish (tid<128) ----
        if (tid < 128) {
            const float* xb = xgp + (t & 1) * 640;
            float gv[4];
#pragma unroll
            for (int g = 0; g < 4; g++) {
                const int row = g * 4 + colL;
                float s = bias_r[g] + xb[row * 40 + b_act];
#pragma unroll
                for (int w2 = 0; w2 < 8; w2++)
                    s += redp[w2 * 640 + row * 40 + b_act];
                gv[g] = s;
            }
            float ig = sigf(gv[0]);
            float fg = sigf(gv[1]);
            float gt = tanhfast(gv[2]);
            float og = sigf(gv[3]);
            float cn = fmaf(fg, c_reg, ig * gt);
            float hn = og * tanhfast(cn);
            c_reg = cn;

            g_hp[(t + 1) & 1][b_act * HH + colG] = packhl(hn);
            __threadfence();
            __syncthreads();
            if (tid == 0) *(volatile int*)&g_flag[cta * 32] = F + t + 2;

            // output stores off the critical path
            out[((size_t)b_act * TT + t) * HH + colG] = hn;
            if (t == TT - 1 && tails) {
                out[BTH + (long long)b_act * HH + colG] = hn;
                out[BTH + (long long)BB * HH + (long long)b_act * HH + colG] = cn;
            }
        } else {
            __threadfence();
            __syncthreads();
        }
    }
}

// ---------------------------------------------------------------------------
// Inputs (metadata order): x, h0, c0, W_ih, W_hh, b_ih, b_hh
// Output: concat(result[B,T,H], h_f[1,B,H], c_f[1,B,H])
// ---------------------------------------------------------------------------
extern "C" void kernel_launch(void* const* d_in, const int* in_sizes, int n_in,
                              void* d_out, int out_size) {
    const float* x   = (const float*)d_in[0];
    const float* h0  = (const float*)d_in[1];
    const float* c0  = (const float*)d_in[2];
    const float* Wih = (const float*)d_in[3];
    const float* Whh = (const float*)d_in[4];
    const float* bih = (const float*)d_in[5];
    const float* bhh = (const float*)d_in[6];
    float* out = (float*)d_out;

    cudaFuncSetAttribute(lstm_rec, cudaFuncAttributeMaxDynamicSharedMemorySize, SM_TOT);

    conv_kernel<<<1024, 256>>>(x, Wih);
    xg_kernel<<<148, NTH>>>();
    lstm_rec<<<NREC, NTH, SM_TOT>>>(h0, c0, Whh, bih, bhh, out, (long long)out_size);
}

// round 12
// speedup vs baseline: 2.0434x; 1.6136x over previous
#include <cuda_runtime.h>
#include <cuda_bf16.h>
#include <cstdint>

#define BB 32
#define TT 2048
#define II 256
#define HH 512
#define GG 2048   // 4*H

#define NCTA_R 64
#define NTH  256

// Scratch (device globals — zero-initialized; no runtime allocation)
__device__ __nv_bfloat16 g_xbhi[BB * TT * II];    // x hi plane [b][t][i] (32 MB)
__device__ __nv_bfloat16 g_xblo[BB * TT * II];    // x lo plane (32 MB)
__device__ uint32_t g_hp[2][BB * HH];             // ping-pong hidden, packed hi|lo,
                                                  // BLOCKED layout: [cta][b][8cols]
__device__ int g_flag[NCTA_R * 32];               // per-CTA monotonic flags (128B apart)

// ---------------------------------------------------------------------------
// helpers
// ---------------------------------------------------------------------------
__device__ __forceinline__ void split2(float x, float y, uint32_t& hi, uint32_t& lo) {
    __nv_bfloat162 h = __floats2bfloat162_rn(x, y);
    float rx = x - __bfloat162float(h.x);
    float ry = y - __bfloat162float(h.y);
    __nv_bfloat162 l = __floats2bfloat162_rn(rx, ry);
    hi = *(uint32_t*)&h;
    lo = *(uint32_t*)&l;
}

__device__ __forceinline__ uint32_t packhl(float v) {
    __nv_bfloat16 h = __float2bfloat16(v);
    float r = v - __bfloat162float(h);
    __nv_bfloat16 lo = __float2bfloat16(r);
    unsigned short uh = *reinterpret_cast<unsigned short*>(&h);
    unsigned short ul = *reinterpret_cast<unsigned short*>(&lo);
    return (uint32_t)uh | ((uint32_t)ul << 16);
}

__device__ __forceinline__ void mma_bf16(float* c,
                                         uint32_t a0, uint32_t a1, uint32_t a2, uint32_t a3,
                                         uint32_t b0, uint32_t b1) {
    asm volatile(
        "mma.sync.aligned.m16n8k16.row.col.f32.bf16.bf16.f32 "
        "{%0,%1,%2,%3}, {%4,%5,%6,%7}, {%8,%9}, {%0,%1,%2,%3};"
        : "+f"(c[0]), "+f"(c[1]), "+f"(c[2]), "+f"(c[3])
        : "r"(a0), "r"(a1), "r"(a2), "r"(a3), "r"(b0), "r"(b1));
}

__device__ __forceinline__ float sigf(float v) {
    return __fdividef(1.0f, 1.0f + __expf(-v));
}
__device__ __forceinline__ float tanhfast(float v) {
    return __fdividef(2.0f, 1.0f + __expf(-2.0f * v)) - 1.0f;
}

__device__ __forceinline__ uint32_t smem_u32(const void* p) {
    uint32_t a;
    asm("{ .reg .u64 t; cvta.to.shared.u64 t, %1; cvt.u32.u64 %0, t; }" : "=r"(a) : "l"(p));
    return a;
}
__device__ __forceinline__ void cp_async8(uint32_t dst, const void* src) {
    asm volatile("cp.async.ca.shared.global [%0], [%1], 8;" :: "r"(dst), "l"(src) : "memory");
}

// release/acquire flag ops (GPU scope)
__device__ __forceinline__ int ld_acq(const int* p) {
    int v;
    asm volatile("ld.acquire.gpu.global.b32 %0, [%1];" : "=r"(v) : "l"(p) : "memory");
    return v;
}
__device__ __forceinline__ void st_rel(int* p, int v) {
    asm volatile("st.release.gpu.global.b32 [%0], %1;" :: "l"(p), "r"(v) : "memory");
}

// h B-fragments from BLOCKED packed layout: addr(b,col) = ((col>>3)*32 + b)*8 + (col&7)
// f[nt][0..3] = bh0, bh1, bl0, bl1 for batch rows 8nt+g4 at k..k+15.
__device__ __forceinline__ void load_hfrag(uint32_t f[4][4], const uint32_t* __restrict__ hp,
                                           int g4, int k) {
    const uint32_t* base = hp + ((k >> 3) * 32) * 8 + (k & 7);
#pragma unroll
    for (int nt = 0; nt < 4; nt++) {
        const uint32_t* rp = base + (8 * nt + g4) * 8;
        uint2 ca = __ldcg((const uint2*)rp);          // k, k+1
        uint2 cb = __ldcg((const uint2*)(rp + 256));  // k+8, k+9
        f[nt][0] = __byte_perm(ca.x, ca.y, 0x5410);
        f[nt][2] = __byte_perm(ca.x, ca.y, 0x7632);
        f[nt][1] = __byte_perm(cb.x, cb.y, 0x5410);
        f[nt][3] = __byte_perm(cb.x, cb.y, 0x7632);
    }
}

// ---------------------------------------------------------------------------
// Kernel 0: convert x to bf16 hi/lo planes (layout preserved [b][t][i])
// ---------------------------------------------------------------------------
__global__ void __launch_bounds__(256) xconv_kernel(const float* __restrict__ x) {
    const float2* src = (const float2*)x;
    uint32_t* dhi = (uint32_t*)g_xbhi;
    uint32_t* dlo = (uint32_t*)g_xblo;
    size_t n2 = (size_t)BB * TT * II / 2;
    for (size_t i = blockIdx.x * 256 + threadIdx.x; i < n2; i += (size_t)gridDim.x * 256) {
        float2 v = src[i];
        uint32_t hi, lo;
        split2(v.x, v.y, hi, lo);
        dhi[i] = hi;
        dlo[i] = lo;
    }
}

// smem layout (bytes)
#define SM_X   0                     // 2 bufs x (hi 16896 + lo 16896) = 67584
#define XPITCH 528
#define XPLANE 16896                 // 32 * 528
#define XBUF   33792                 // hi+lo
#define SM_RED 67584                 // 8*32*36*4 = 36864  (f32 [8][32][36])
#define SM_TOT 104448

// ---------------------------------------------------------------------------
// Fused persistent LSTM. 64 CTAs x 256 threads (8 warps).
// CTA owns 8 H-cols -> 32 gate rows (r = gate*8 + colL).
// gates = W_hh*h (K=512, 8-way K-split) + W_ih*x[t] (K=256) + bias,
// m16n8k16 bf16 3-pass; W frags in registers; h B-frags loaded directly
// from packed BLOCKED global.
// Sync: per-CTA monotonic flags, release store / acquire poll (no membar).
// ---------------------------------------------------------------------------
__global__ void __launch_bounds__(NTH, 1) lstm_fused(
    const float* __restrict__ h0,
    const float* __restrict__ c0,
    const float* __restrict__ Wih,
    const float* __restrict__ Whh,
    const float* __restrict__ bih,
    const float* __restrict__ bhh,
    float* __restrict__ out,
    long long out_size)
{
    extern __shared__ char smem[];
    float* redp = (float*)(smem + SM_RED);

    const int tid = threadIdx.x;
    const int cta = blockIdx.x;
    const int col0 = cta * 8;

    const int w  = tid >> 5;   // warp: h K-slice [64w, 64w+64), x K-slice [32w, 32w+32)
    const int l  = tid & 31;
    const int g4 = l >> 2;
    const int t4 = l & 3;

    // --- W_hh fragments (hi/lo) in registers ---
    uint32_t whi[2][4][4], wlo[2][4][4];
#pragma unroll
    for (int mt = 0; mt < 2; mt++)
#pragma unroll
        for (int kt = 0; kt < 4; kt++) {
            const int k = 64 * w + 16 * kt + 2 * t4;
            const int r0 = mt * 16 + g4;
            const int r1 = r0 + 8;
            const int grow0 = (r0 >> 3) * HH + col0 + (r0 & 7);
            const int grow1 = (r1 >> 3) * HH + col0 + (r1 & 7);
            float2 v;
            v = *(const float2*)(Whh + (size_t)grow0 * HH + k);
            split2(v.x, v.y, whi[mt][kt][0], wlo[mt][kt][0]);
            v = *(const float2*)(Whh + (size_t)grow1 * HH + k);
            split2(v.x, v.y, whi[mt][kt][1], wlo[mt][kt][1]);
            v = *(const float2*)(Whh + (size_t)grow0 * HH + k + 8);
            split2(v.x, v.y, whi[mt][kt][2], wlo[mt][kt][2]);
            v = *(const float2*)(Whh + (size_t)grow1 * HH + k + 8);
            split2(v.x, v.y, whi[mt][kt][3], wlo[mt][kt][3]);
        }

    // --- W_ih fragments (hi/lo) in registers ---
    uint32_t xwhi[2][2][4], xwlo[2][2][4];
#pragma unroll
    for (int mt = 0; mt < 2; mt++)
#pragma unroll
        for (int kt = 0; kt < 2; kt++) {
            const int k = 32 * w + 16 * kt + 2 * t4;
            const int r0 = mt * 16 + g4;
            const int r1 = r0 + 8;
            const int grow0 = (r0 >> 3) * HH + col0 + (r0 & 7);
            const int grow1 = (r1 >> 3) * HH + col0 + (r1 & 7);
            float2 v;
            v = *(const float2*)(Wih + (size_t)grow0 * II + k);
            split2(v.x, v.y, xwhi[mt][kt][0], xwlo[mt][kt][0]);
            v = *(const float2*)(Wih + (size_t)grow1 * II + k);
            split2(v.x, v.y, xwhi[mt][kt][1], xwlo[mt][kt][1]);
            v = *(const float2*)(Wih + (size_t)grow0 * II + k + 8);
            split2(v.x, v.y, xwhi[mt][kt][2], xwlo[mt][kt][2]);
            v = *(const float2*)(Wih + (size_t)grow1 * II + k + 8);
            split2(v.x, v.y, xwhi[mt][kt][3], xwlo[mt][kt][3]);
        }

    // --- activation identity + per-thread state ---
    const int colL = tid & 7;
    const int b_act = tid >> 3;
    const int colG = col0 + colL;
    float c_reg = c0[b_act * HH + colG];
    float bias_r[4];
#pragma unroll
    for (int g = 0; g < 4; g++)
        bias_r[g] = bih[g * HH + colG] + bhh[g * HH + colG];

    // --- flag base (monotonic across graph replays) ---
    const int F = *(volatile int*)&g_flag[cta * 32];

    // --- stage h0 slice into buffer 0 (blocked layout, fully coalesced) ---
    g_hp[0][cta * 256 + tid] = packhl(h0[b_act * HH + colG]);

    // --- stage x[0] into x buffer 0 via cp.async ---
    {
        char* xb = smem + SM_X;
#pragma unroll
        for (int j = 0; j < 8; j++) {
            int q = tid + NTH * j;
            int row = q >> 6;
            int c8 = q & 63;
            size_t src = ((size_t)row * TT + 0) * II + c8 * 4;
            cp_async8(smem_u32(xb + row * XPITCH + c8 * 8), g_xbhi + src);
            cp_async8(smem_u32(xb + XPLANE + row * XPITCH + c8 * 8), g_xblo + src);
        }
        asm volatile("cp.async.commit_group;" ::: "memory");
        asm volatile("cp.async.wait_all;" ::: "memory");
    }
    __syncthreads();
    if (tid == 0) st_rel(&g_flag[cta * 32], F + 1);

    const long long BTH = (long long)BB * TT * HH;
    const bool tails = (out_size >= BTH + 2LL * BB * HH);

    const int pidx = (8 * w + (l & 7)) * 32;   // producer flag index
    const bool poller = (l < 8);               // only 8 lanes generate poll traffic

    for (int t = 0; t < TT; t++) {
        // ---- issue x[t+1] prefetch FIRST (whole step to land) ----
        if (t + 1 < TT) {
            char* xn = smem + SM_X + ((t + 1) & 1) * XBUF;
#pragma unroll
            for (int j = 0; j < 8; j++) {
                int q = tid + NTH * j;
                int row = q >> 6;
                int c8 = q & 63;
                size_t src = ((size_t)row * TT + (t + 1)) * II + c8 * 4;
                cp_async8(smem_u32(xn + row * XPITCH + c8 * 8), g_xbhi + src);
                cp_async8(smem_u32(xn + XPLANE + row * XPITCH + c8 * 8), g_xblo + src);
            }
            asm volatile("cp.async.commit_group;" ::: "memory");
        }

        // ---- poll producer flags: acquire loads, bare spin, lanes<8 ----
        {
            const int need = F + t + 1;
            while (__any_sync(0xffffffffu,
                              poller && (ld_acq(&g_flag[pidx]) < need)))
                ;
        }
        __syncwarp();   // extend acquire ordering to all lanes of the warp

        const uint32_t* hp = g_hp[t & 1];
        const int kbase = 64 * w + 2 * t4;

        // ---- kick off h frag loads for kt0, kt1 (fly during x MMAs) ----
        uint32_t fA[4][4], fB[4][4];
        load_hfrag(fA, hp, g4, kbase + 0);
        load_hfrag(fB, hp, g4, kbase + 16);

        // ---- x MMAs (48) from smem (latency cover for h LDGs) ----
        float acc[2][4][4] = {};
        {
            char* xb = smem + SM_X + (t & 1) * XBUF;
#pragma unroll
            for (int nt = 0; nt < 4; nt++)
#pragma unroll
                for (int kt = 0; kt < 2; kt++) {
                    uint32_t off = (uint32_t)((g4 + 8 * nt) * XPITCH + (32 * w + 16 * kt + 2 * t4) * 2);
                    uint32_t bh0 = *(const uint32_t*)(xb + off);
                    uint32_t bh1 = *(const uint32_t*)(xb + off + 16);
                    uint32_t bl0 = *(const uint32_t*)(xb + XPLANE + off);
                    uint32_t bl1 = *(const uint32_t*)(xb + XPLANE + off + 16);
#pragma unroll
                    for (int mt = 0; mt < 2; mt++) {
                        mma_bf16(acc[mt][nt], xwhi[mt][kt][0], xwhi[mt][kt][1], xwhi[mt][kt][2], xwhi[mt][kt][3], bh0, bh1);
                        mma_bf16(acc[mt][nt], xwhi[mt][kt][0], xwhi[mt][kt][1], xwhi[mt][kt][2], xwhi[mt][kt][3], bl0, bl1);
                        mma_bf16(acc[mt][nt], xwlo[mt][kt][0], xwlo[mt][kt][1], xwlo[mt][kt][2], xwlo[mt][kt][3], bh0, bh1);
                    }
                }
        }

        // ---- h MMAs, pipelined: consume kt, prefetch kt+2 ----
#define HMMA_KT(F_, KT_) \
        { _Pragma("unroll") \
          for (int nt = 0; nt < 4; nt++) { \
            _Pragma("unroll") \
            for (int mt = 0; mt < 2; mt++) { \
                mma_bf16(acc[mt][nt], whi[mt][KT_][0], whi[mt][KT_][1], whi[mt][KT_][2], whi[mt][KT_][3], F_[nt][0], F_[nt][1]); \
                mma_bf16(acc[mt][nt], whi[mt][KT_][0], whi[mt][KT_][1], whi[mt][KT_][2], whi[mt][KT_][3], F_[nt][2], F_[nt][3]); \
                mma_bf16(acc[mt][nt], wlo[mt][KT_][0], wlo[mt][KT_][1], wlo[mt][KT_][2], wlo[mt][KT_][3], F_[nt][0], F_[nt][1]); \
            } } }

        HMMA_KT(fA, 0);
        load_hfrag(fA, hp, g4, kbase + 32);
        HMMA_KT(fB, 1);
        load_hfrag(fB, hp, g4, kbase + 48);
        HMMA_KT(fA, 2);
        HMMA_KT(fB, 3);
#undef HMMA_KT

        // ---- store split-K partials: red[w][row][b], pitch 36 ----
        {
            float* rw = redp + w * 1152;
#pragma unroll
            for (int mt = 0; mt < 2; mt++)
#pragma unroll
                for (int nt = 0; nt < 4; nt++) {
                    int row0 = mt * 16 + g4;
                    int cc = 8 * nt + 2 * t4;
                    *(float2*)&rw[row0 * 36 + cc] = make_float2(acc[mt][nt][0], acc[mt][nt][1]);
                    *(float2*)&rw[(row0 + 8) * 36 + cc] = make_float2(acc[mt][nt][2], acc[mt][nt][3]);
                }
        }
        __syncthreads();

        // ---- reduce + activations + publish ----
        {
            float gv[4];
#pragma unroll
            for (int g = 0; g < 4; g++) {
                float s = bias_r[g];
                const int row = g * 8 + colL;
#pragma unroll
                for (int w2 = 0; w2 < 8; w2++)
                    s += redp[w2 * 1152 + row * 36 + b_act];
                gv[g] = s;
            }
            float ig = sigf(gv[0]);
            float fg = sigf(gv[1]);
            float gt = tanhfast(gv[2]);
            float og = sigf(gv[3]);
            float cn = fmaf(fg, c_reg, ig * gt);
            float hn = og * tanhfast(cn);
            c_reg = cn;

            // publish h: one coalesced 1KB burst per CTA (blocked layout)
            g_hp[(t + 1) & 1][cta * 256 + tid] = packhl(hn);
            asm volatile("cp.async.wait_all;" ::: "memory");
            __syncthreads();                 // orders all threads' STGs before the release
            if (tid == 0) st_rel(&g_flag[cta * 32], F + t + 2);

            // output stores off the critical path
            out[((size_t)b_act * TT + t) * HH + colG] = hn;
            if (t == TT - 1 && tails) {
                out[BTH + (long long)b_act * HH + colG] = hn;
                out[BTH + (long long)BB * HH + (long long)b_act * HH + colG] = cn;
            }
        }
    }
}

// ---------------------------------------------------------------------------
// Inputs (metadata order): x, h0, c0, W_ih, W_hh, b_ih, b_hh
// Output: concat(result[B,T,H], h_f[1,B,H], c_f[1,B,H])
// ---------------------------------------------------------------------------
extern "C" void kernel_launch(void* const* d_in, const int* in_sizes, int n_in,
                              void* d_out, int out_size) {
    const float* x   = (const float*)d_in[0];
    const float* h0  = (const float*)d_in[1];
    const float* c0  = (const float*)d_in[2];
    const float* Wih = (const float*)d_in[3];
    const float* Whh = (const float*)d_in[4];
    const float* bih = (const float*)d_in[5];
    const float* bhh = (const float*)d_in[6];
    float* out = (float*)d_out;

    cudaFuncSetAttribute(lstm_fused, cudaFuncAttributeMaxDynamicSharedMemorySize, SM_TOT);

    xconv_kernel<<<2048, 256>>>(x);
    lstm_fused<<<NCTA_R, NTH, SM_TOT>>>(h0, c0, Wih, Whh, bih, bhh, out, (long long)out_size);
}

// round 14
// speedup vs baseline: 2.3316x; 1.1411x over previous
#include <cuda_runtime.h>
#include <cuda_bf16.h>
#include <cstdint>

#define BB 32
#define TT 2048
#define II 256
#define HH 512
#define GG 2048   // 4*H

#define NCTA_R 128
#define NTH  256

// Scratch (device globals — zero-initialized; no runtime allocation)
__device__ __nv_bfloat16 g_xbhi[BB * TT * II];    // x hi plane [b][t][i] (32 MB)
__device__ __nv_bfloat16 g_xblo[BB * TT * II];    // x lo plane (32 MB)
__device__ uint32_t g_hp[2][BB * HH];             // ping-pong hidden, packed hi|lo,
                                                  // BLOCKED: [cta][b][4cols]
__device__ int g_flag[NCTA_R * 32];               // per-CTA monotonic flags (128B apart)

// ---------------------------------------------------------------------------
// helpers
// ---------------------------------------------------------------------------
__device__ __forceinline__ void split2(float x, float y, uint32_t& hi, uint32_t& lo) {
    __nv_bfloat162 h = __floats2bfloat162_rn(x, y);
    float rx = x - __bfloat162float(h.x);
    float ry = y - __bfloat162float(h.y);
    __nv_bfloat162 l = __floats2bfloat162_rn(rx, ry);
    hi = *(uint32_t*)&h;
    lo = *(uint32_t*)&l;
}

__device__ __forceinline__ uint32_t packhl(float v) {
    __nv_bfloat16 h = __float2bfloat16(v);
    float r = v - __bfloat162float(h);
    __nv_bfloat16 lo = __float2bfloat16(r);
    unsigned short uh = *reinterpret_cast<unsigned short*>(&h);
    unsigned short ul = *reinterpret_cast<unsigned short*>(&lo);
    return (uint32_t)uh | ((uint32_t)ul << 16);
}

__device__ __forceinline__ void mma_bf16(float* c,
                                         uint32_t a0, uint32_t a1, uint32_t a2, uint32_t a3,
                                         uint32_t b0, uint32_t b1) {
    asm volatile(
        "mma.sync.aligned.m16n8k16.row.col.f32.bf16.bf16.f32 "
        "{%0,%1,%2,%3}, {%4,%5,%6,%7}, {%8,%9}, {%0,%1,%2,%3};"
        : "+f"(c[0]), "+f"(c[1]), "+f"(c[2]), "+f"(c[3])
        : "r"(a0), "r"(a1), "r"(a2), "r"(a3), "r"(b0), "r"(b1));
}

__device__ __forceinline__ float sigf(float v) {
    return __fdividef(1.0f, 1.0f + __expf(-v));
}
__device__ __forceinline__ float tanhfast(float v) {
    return __fdividef(2.0f, 1.0f + __expf(-2.0f * v)) - 1.0f;
}

__device__ __forceinline__ uint32_t smem_u32(const void* p) {
    uint32_t a;
    asm("{ .reg .u64 t; cvta.to.shared.u64 t, %1; cvt.u32.u64 %0, t; }" : "=r"(a) : "l"(p));
    return a;
}
__device__ __forceinline__ void cp_async8(uint32_t dst, const void* src) {
    asm volatile("cp.async.ca.shared.global [%0], [%1], 8;" :: "r"(dst), "l"(src) : "memory");
}

// release/acquire flag ops (GPU scope)
__device__ __forceinline__ int ld_acq(const int* p) {
    int v;
    asm volatile("ld.acquire.gpu.global.b32 %0, [%1];" : "=r"(v) : "l"(p) : "memory");
    return v;
}
__device__ __forceinline__ void st_rel(int* p, int v) {
    asm volatile("st.release.gpu.global.b32 [%0], %1;" :: "l"(p), "r"(v) : "memory");
}

// h B-fragments from BLOCKED packed layout: addr(b,col) = (col>>2)*128 + b*4 + (col&3)
// f[nt][0..3] = bh0, bh1, bl0, bl1 for batch rows 8nt+g4 at k0..k0+15.
__device__ __forceinline__ void load_hfrag(uint32_t f[4][4], const uint32_t* __restrict__ hp,
                                           int g4, int t4, int k0) {
    const uint32_t* base = hp + ((k0 + 2 * t4) >> 2) * 128 + ((2 * t4) & 3);
#pragma unroll
    for (int nt = 0; nt < 4; nt++) {
        const uint32_t* rp = base + (8 * nt + g4) * 4;
        uint2 ca = __ldcg((const uint2*)rp);          // cols k0+2t4, +1
        uint2 cb = __ldcg((const uint2*)(rp + 256));  // cols k0+2t4+8, +9
        f[nt][0] = __byte_perm(ca.x, ca.y, 0x5410);
        f[nt][2] = __byte_perm(ca.x, ca.y, 0x7632);
        f[nt][1] = __byte_perm(cb.x, cb.y, 0x5410);
        f[nt][3] = __byte_perm(cb.x, cb.y, 0x7632);
    }
}

// ---------------------------------------------------------------------------
// Kernel 0: convert x to bf16 hi/lo planes (layout preserved [b][t][i])
// ---------------------------------------------------------------------------
__global__ void __launch_bounds__(256) xconv_kernel(const float* __restrict__ x) {
    const float2* src = (const float2*)x;
    uint32_t* dhi = (uint32_t*)g_xbhi;
    uint32_t* dlo = (uint32_t*)g_xblo;
    size_t n2 = (size_t)BB * TT * II / 2;
    for (size_t i = blockIdx.x * 256 + threadIdx.x; i < n2; i += (size_t)gridDim.x * 256) {
        float2 v = src[i];
        uint32_t hi, lo;
        split2(v.x, v.y, hi, lo);
        dhi[i] = hi;
        dlo[i] = lo;
    }
}

// smem layout (bytes)
#define SM_X   0                     // 2 bufs x (hi 16896 + lo 16896) = 67584
#define XPITCH 528
#define XPLANE 16896                 // 32 * 528
#define XBUF   33792                 // hi+lo
#define SM_RED 67584                 // 8 * 16*40 * 4 = 20480  (f32 [8][16][40])
#define SM_TOT 88064

// ---------------------------------------------------------------------------
// Fused persistent LSTM. 128 CTAs x 256 threads (8 warps).
// CTA owns 4 H-cols -> 16 gate rows (r = gate*4 + colL), M=16.
// gates = W_hh*h (K=512, 8-way K-split, 48 MMAs/warp) + W_ih*x[t] (24 MMAs)
// + bias; m16n8k16 bf16 3-pass; W frags in registers; h B-frags direct
// from packed BLOCKED global.
// Sync: per-CTA monotonic flags, release store / acquire poll (no membar).
// ---------------------------------------------------------------------------
__global__ void __launch_bounds__(NTH, 1) lstm_fused(
    const float* __restrict__ h0,
    const float* __restrict__ c0,
    const float* __restrict__ Wih,
    const float* __restrict__ Whh,
    const float* __restrict__ bih,
    const float* __restrict__ bhh,
    float* __restrict__ out,
    long long out_size)
{
    extern __shared__ char smem[];
    float* redp = (float*)(smem + SM_RED);

    const int tid = threadIdx.x;
    const int cta = blockIdx.x;
    const int col0 = cta * 4;

    const int w  = tid >> 5;   // warp: h K-slice [64w, 64w+64), x K-slice [32w, 32w+32)
    const int l  = tid & 31;
    const int g4 = l >> 2;
    const int t4 = l & 3;

    // --- W_hh fragments (hi/lo) in registers: 16 rows x warp's K=64 ---
    uint32_t whi[4][4], wlo[4][4];
#pragma unroll
    for (int kt = 0; kt < 4; kt++) {
        const int k = 64 * w + 16 * kt + 2 * t4;
        const int r0 = g4;
        const int r1 = g4 + 8;
        const int grow0 = (r0 >> 2) * HH + col0 + (r0 & 3);
        const int grow1 = (r1 >> 2) * HH + col0 + (r1 & 3);
        float2 v;
        v = *(const float2*)(Whh + (size_t)grow0 * HH + k);
        split2(v.x, v.y, whi[kt][0], wlo[kt][0]);
        v = *(const float2*)(Whh + (size_t)grow1 * HH + k);
        split2(v.x, v.y, whi[kt][1], wlo[kt][1]);
        v = *(const float2*)(Whh + (size_t)grow0 * HH + k + 8);
        split2(v.x, v.y, whi[kt][2], wlo[kt][2]);
        v = *(const float2*)(Whh + (size_t)grow1 * HH + k + 8);
        split2(v.x, v.y, whi[kt][3], wlo[kt][3]);
    }

    // --- W_ih fragments (hi/lo) in registers ---
    uint32_t xwhi[2][4], xwlo[2][4];
#pragma unroll
    for (int kt = 0; kt < 2; kt++) {
        const int k = 32 * w + 16 * kt + 2 * t4;
        const int r0 = g4;
        const int r1 = g4 + 8;
        const int grow0 = (r0 >> 2) * HH + col0 + (r0 & 3);
        const int grow1 = (r1 >> 2) * HH + col0 + (r1 & 3);
        float2 v;
        v = *(const float2*)(Wih + (size_t)grow0 * II + k);
        split2(v.x, v.y, xwhi[kt][0], xwlo[kt][0]);
        v = *(const float2*)(Wih + (size_t)grow1 * II + k);
        split2(v.x, v.y, xwhi[kt][1], xwlo[kt][1]);
        v = *(const float2*)(Wih + (size_t)grow0 * II + k + 8);
        split2(v.x, v.y, xwhi[kt][2], xwlo[kt][2]);
        v = *(const float2*)(Wih + (size_t)grow1 * II + k + 8);
        split2(v.x, v.y, xwhi[kt][3], xwlo[kt][3]);
    }

    // --- activation identity + per-thread state (tid<128 only) ---
    const int colL = tid & 3;
    const int b_act = tid >> 2;      // 0..31 for tid<128
    const int colG = col0 + colL;
    float c_reg = 0.f, bias_r[4] = {};
    if (tid < 128) {
        c_reg = c0[b_act * HH + colG];
#pragma unroll
        for (int g = 0; g < 4; g++)
            bias_r[g] = bih[g * HH + colG] + bhh[g * HH + colG];
    }

    // --- flag base (monotonic across graph replays) ---
    const int F = *(volatile int*)&g_flag[cta * 32];

    // --- stage h0 slice into buffer 0 (blocked, 512B coalesced) ---
    if (tid < 128) g_hp[0][cta * 128 + tid] = packhl(h0[b_act * HH + colG]);

    // --- stage x[0] into x buffer 0 via cp.async ---
    {
        char* xb = smem + SM_X;
#pragma unroll
        for (int j = 0; j < 8; j++) {
            int q = tid + NTH * j;
            int row = q >> 6;
            int c8 = q & 63;
            size_t src = ((size_t)row * TT + 0) * II + c8 * 4;
            cp_async8(smem_u32(xb + row * XPITCH + c8 * 8), g_xbhi + src);
            cp_async8(smem_u32(xb + XPLANE + row * XPITCH + c8 * 8), g_xblo + src);
        }
        asm volatile("cp.async.commit_group;" ::: "memory");
        asm volatile("cp.async.wait_all;" ::: "memory");
    }
    __syncthreads();
    if (tid == 0) st_rel(&g_flag[cta * 32], F + 1);

    const long long BTH = (long long)BB * TT * HH;
    const bool tails = (out_size >= BTH + 2LL * BB * HH);

    const int pidx = (16 * w + (l & 15)) * 32;   // producer flag index
    const bool poller = (l < 16);                // 16 lanes cover 16 producers

    for (int t = 0; t < TT; t++) {
        // ---- issue x[t+1] prefetch FIRST (whole step to land) ----
        if (t + 1 < TT) {
            char* xn = smem + SM_X + ((t + 1) & 1) * XBUF;
#pragma unroll
            for (int j = 0; j < 8; j++) {
                int q = tid + NTH * j;
                int row = q >> 6;
                int c8 = q & 63;
                size_t src = ((size_t)row * TT + (t + 1)) * II + c8 * 4;
                cp_async8(smem_u32(xn + row * XPITCH + c8 * 8), g_xbhi + src);
                cp_async8(smem_u32(xn + XPLANE + row * XPITCH + c8 * 8), g_xblo + src);
            }
            asm volatile("cp.async.commit_group;" ::: "memory");
        }

        // ---- poll producer flags: acquire loads, bare spin, lanes<16 ----
        {
            const int need = F + t + 1;
            while (__any_sync(0xffffffffu,
                              poller && (ld_acq(&g_flag[pidx]) < need)))
                ;
        }
        __syncwarp();

        const uint32_t* hp = g_hp[t & 1];
        const int kbase = 64 * w;

        // ---- kick off h frag loads for kt0, kt1 (fly during x MMAs) ----
        uint32_t fA[4][4], fB[4][4];
        load_hfrag(fA, hp, g4, t4, kbase + 0);
        load_hfrag(fB, hp, g4, t4, kbase + 16);

        // ---- x MMAs (24) from smem (latency cover for h LDGs) ----
        float acc[4][4] = {};
        {
            char* xb = smem + SM_X + (t & 1) * XBUF;
#pragma unroll
            for (int nt = 0; nt < 4; nt++)
#pragma unroll
                for (int kt = 0; kt < 2; kt++) {
                    uint32_t off = (uint32_t)((g4 + 8 * nt) * XPITCH + (32 * w + 16 * kt + 2 * t4) * 2);
                    uint32_t bh0 = *(const uint32_t*)(xb + off);
                    uint32_t bh1 = *(const uint32_t*)(xb + off + 16);
                    uint32_t bl0 = *(const uint32_t*)(xb + XPLANE + off);
                    uint32_t bl1 = *(const uint32_t*)(xb + XPLANE + off + 16);
                    mma_bf16(acc[nt], xwhi[kt][0], xwhi[kt][1], xwhi[kt][2], xwhi[kt][3], bh0, bh1);
                    mma_bf16(acc[nt], xwhi[kt][0], xwhi[kt][1], xwhi[kt][2], xwhi[kt][3], bl0, bl1);
                    mma_bf16(acc[nt], xwlo[kt][0], xwlo[kt][1], xwlo[kt][2], xwlo[kt][3], bh0, bh1);
                }
        }

        // ---- h MMAs (48), pipelined: consume kt, prefetch kt+2 ----
#define HMMA_KT(F_, KT_) \
        { _Pragma("unroll") \
          for (int nt = 0; nt < 4; nt++) { \
                mma_bf16(acc[nt], whi[KT_][0], whi[KT_][1], whi[KT_][2], whi[KT_][3], F_[nt][0], F_[nt][1]); \
                mma_bf16(acc[nt], whi[KT_][0], whi[KT_][1], whi[KT_][2], whi[KT_][3], F_[nt][2], F_[nt][3]); \
                mma_bf16(acc[nt], wlo[KT_][0], wlo[KT_][1], wlo[KT_][2], wlo[KT_][3], F_[nt][0], F_[nt][1]); \
          } }

        HMMA_KT(fA, 0);
        load_hfrag(fA, hp, g4, t4, kbase + 32);
        HMMA_KT(fB, 1);
        load_hfrag(fB, hp, g4, t4, kbase + 48);
        HMMA_KT(fA, 2);
        HMMA_KT(fB, 3);
#undef HMMA_KT

        // ---- store split-K partials: red[w][row][b], pitch 40 ----
        {
            float* rw = redp + w * 640;
#pragma unroll
            for (int nt = 0; nt < 4; nt++) {
                int cc = 8 * nt + 2 * t4;
                *(float2*)&rw[g4 * 40 + cc] = make_float2(acc[nt][0], acc[nt][1]);
                *(float2*)&rw[(g4 + 8) * 40 + cc] = make_float2(acc[nt][2], acc[nt][3]);
            }
        }
        __syncthreads();

        // ---- reduce + activations + publish (tid<128) ----
        float hn = 0.f, cn = 0.f;
        if (tid < 128) {
            float gv[4];
#pragma unroll
            for (int g = 0; g < 4; g++) {
                float s = bias_r[g];
                const int row = g * 4 + colL;
#pragma unroll
                for (int w2 = 0; w2 < 8; w2++)
                    s += redp[w2 * 640 + row * 40 + b_act];
                gv[g] = s;
            }
            float ig = sigf(gv[0]);
            float fg = sigf(gv[1]);
            float gt = tanhfast(gv[2]);
            float og = sigf(gv[3]);
            cn = fmaf(fg, c_reg, ig * gt);
            hn = og * tanhfast(cn);
            c_reg = cn;

            // publish h: one coalesced 512B burst per CTA (blocked layout)
            g_hp[(t + 1) & 1][cta * 128 + tid] = packhl(hn);
        }
        asm volatile("cp.async.wait_all;" ::: "memory");
        __syncthreads();                 // orders all threads' STGs before the release
        if (tid == 0) st_rel(&g_flag[cta * 32], F + t + 2);

        // output stores off the critical path
        if (tid < 128) {
            out[((size_t)b_act * TT + t) * HH + colG] = hn;
            if (t == TT - 1 && tails) {
                out[BTH + (long long)b_act * HH + colG] = hn;
                out[BTH + (long long)BB * HH + (long long)b_act * HH + colG] = cn;
            }
        }
    }
}

// ---------------------------------------------------------------------------
// Inputs (metadata order): x, h0, c0, W_ih, W_hh, b_ih, b_hh
// Output: concat(result[B,T,H], h_f[1,B,H], c_f[1,B,H])
// ---------------------------------------------------------------------------
extern "C" void kernel_launch(void* const* d_in, const int* in_sizes, int n_in,
                              void* d_out, int out_size) {
    const float* x   = (const float*)d_in[0];
    const float* h0  = (const float*)d_in[1];
    const float* c0  = (const float*)d_in[2];
    const float* Wih = (const float*)d_in[3];
    const float* Whh = (const float*)d_in[4];
    const float* bih = (const float*)d_in[5];
    const float* bhh = (const float*)d_in[6];
    float* out = (float*)d_out;

    cudaFuncSetAttribute(lstm_fused, cudaFuncAttributeMaxDynamicSharedMemorySize, SM_TOT);

    xconv_kernel<<<2048, 256>>>(x);
    lstm_fused<<<NCTA_R, NTH, SM_TOT>>>(h0, c0, Wih, Whh, bih, bhh, out, (long long)out_size);
}